// round 1
// baseline (speedup 1.0000x reference)
#include <cuda_runtime.h>

#define T_TOK 16384
#define DIM   1024
#define NE    8
#define FDIM  4096

#define BM 64
#define BN 64
#define BK 16

// ---- device scratch (static globals: no allocation inside kernel_launch) ----
__device__ int   g_idx[T_TOK];
__device__ int   g_counts[NE];
__device__ int   g_offsets[NE + 1];
__device__ int   g_cursor[NE];
__device__ int   g_perm[T_TOK];
__device__ float g_h[(size_t)T_TOK * FDIM];   // 256 MB expert-hidden scratch

// ---------------------------------------------------------------- init
__global__ void init_kernel() {
    int t = threadIdx.x;
    if (t < NE) { g_counts[t] = 0; g_cursor[t] = 0; }
}

// ---------------------------------------------------------------- router
// one block (8 warps) per token; warp w computes logit for expert w.
__global__ __launch_bounds__(256) void router_kernel(
    const float* __restrict__ x,
    const float* __restrict__ rw,
    const float* __restrict__ rb)
{
    int t = blockIdx.x;
    int w = threadIdx.x >> 5;
    int l = threadIdx.x & 31;
    const float* xr = x + (size_t)t * DIM;

    float s = 0.f;
    for (int d = l; d < DIM; d += 32)
        s += xr[d] * rw[d * NE + w];
    #pragma unroll
    for (int o = 16; o; o >>= 1)
        s += __shfl_down_sync(0xffffffffu, s, o);

    __shared__ float lg[NE];
    if (l == 0) lg[w] = s + rb[w];
    __syncthreads();

    if (threadIdx.x == 0) {
        int best = 0; float bv = lg[0];
        #pragma unroll
        for (int e = 1; e < NE; e++)
            if (lg[e] > bv) { bv = lg[e]; best = e; }   // strict > == argmax-first
        g_idx[t] = best;
        atomicAdd(&g_counts[best], 1);
    }
}

// ---------------------------------------------------------------- prefix + lb loss
__global__ void prefix_kernel(float* __restrict__ out, int out_size) {
    if (threadIdx.x == 0) {
        int acc = 0;
        float lb = 0.f;
        for (int e = 0; e < NE; e++) {
            g_offsets[e] = acc;
            acc += g_counts[e];
            float u = (float)g_counts[e] / (float)T_TOK - 1.0f / (float)NE;
            lb += u * u;
        }
        g_offsets[NE] = acc;
        lb /= (float)NE;
        if (out_size > T_TOK * DIM)
            out[(size_t)T_TOK * DIM] = lb;
    }
}

// ---------------------------------------------------------------- scatter -> perm
__global__ void scatter_kernel() {
    int t = blockIdx.x * blockDim.x + threadIdx.x;
    if (t < T_TOK) {
        int e = g_idx[t];
        int p = atomicAdd(&g_cursor[e], 1);
        g_perm[g_offsets[e] + p] = t;
    }
}

// ---------------------------------------------------------------- grouped GEMM 1
// H[perm-rows] = relu( X_gather @ W1[e] + b1[e] ),  K = DIM
__global__ __launch_bounds__(256) void gemm1_kernel(
    const float* __restrict__ x,
    const float* __restrict__ w1,
    const float* __restrict__ b1)
{
    int e = blockIdx.z;
    int seg0 = g_offsets[e], seg1 = g_offsets[e + 1];
    int m0 = seg0 + blockIdx.y * BM;
    if (m0 >= seg1) return;
    int n0   = blockIdx.x * BN;
    int mcnt = min(BM, seg1 - m0);

    int tid = threadIdx.x;
    int tx = tid & 15, ty = tid >> 4;

    __shared__ float As[BK][BM + 4];
    __shared__ float Bs[BK][BN];

    // A load mapping: float4 along K
    int am = tid >> 2;
    int ak = (tid & 3) * 4;
    const float* arow = (am < mcnt) ? (x + (size_t)g_perm[m0 + am] * DIM) : nullptr;

    // B load mapping: float4 along N
    int bk = tid >> 4;
    int bn = (tid & 15) * 4;
    const float* wp = w1 + (size_t)e * DIM * FDIM;

    float acc[4][4];
    #pragma unroll
    for (int i = 0; i < 4; i++)
        #pragma unroll
        for (int j = 0; j < 4; j++) acc[i][j] = 0.f;

    for (int k0 = 0; k0 < DIM; k0 += BK) {
        float4 av = make_float4(0.f, 0.f, 0.f, 0.f);
        if (arow) av = *(const float4*)(arow + k0 + ak);
        As[ak + 0][am] = av.x;
        As[ak + 1][am] = av.y;
        As[ak + 2][am] = av.z;
        As[ak + 3][am] = av.w;
        *(float4*)&Bs[bk][bn] =
            *(const float4*)(wp + (size_t)(k0 + bk) * FDIM + n0 + bn);
        __syncthreads();

        #pragma unroll
        for (int k = 0; k < BK; k++) {
            float4 a = *(const float4*)&As[k][ty * 4];
            float4 b = *(const float4*)&Bs[k][tx * 4];
            acc[0][0] += a.x * b.x; acc[0][1] += a.x * b.y; acc[0][2] += a.x * b.z; acc[0][3] += a.x * b.w;
            acc[1][0] += a.y * b.x; acc[1][1] += a.y * b.y; acc[1][2] += a.y * b.z; acc[1][3] += a.y * b.w;
            acc[2][0] += a.z * b.x; acc[2][1] += a.z * b.y; acc[2][2] += a.z * b.z; acc[2][3] += a.z * b.w;
            acc[3][0] += a.w * b.x; acc[3][1] += a.w * b.y; acc[3][2] += a.w * b.z; acc[3][3] += a.w * b.w;
        }
        __syncthreads();
    }

    const float* bb = b1 + e * FDIM + n0;
    #pragma unroll
    for (int i = 0; i < 4; i++) {
        int m = ty * 4 + i;
        if (m < mcnt) {
            float4 v;
            v.x = fmaxf(acc[i][0] + bb[tx * 4 + 0], 0.f);
            v.y = fmaxf(acc[i][1] + bb[tx * 4 + 1], 0.f);
            v.z = fmaxf(acc[i][2] + bb[tx * 4 + 2], 0.f);
            v.w = fmaxf(acc[i][3] + bb[tx * 4 + 3], 0.f);
            *(float4*)(g_h + (size_t)(m0 + m) * FDIM + n0 + tx * 4) = v;
        }
    }
}

// ---------------------------------------------------------------- grouped GEMM 2
// out[perm[row]] = H[row] @ W2[e] + b2[e],  K = FDIM
__global__ __launch_bounds__(256) void gemm2_kernel(
    const float* __restrict__ w2,
    const float* __restrict__ b2,
    float* __restrict__ out)
{
    int e = blockIdx.z;
    int seg0 = g_offsets[e], seg1 = g_offsets[e + 1];
    int m0 = seg0 + blockIdx.y * BM;
    if (m0 >= seg1) return;
    int n0   = blockIdx.x * BN;
    int mcnt = min(BM, seg1 - m0);

    int tid = threadIdx.x;
    int tx = tid & 15, ty = tid >> 4;

    __shared__ float As[BK][BM + 4];
    __shared__ float Bs[BK][BN];

    int am = tid >> 2;
    int ak = (tid & 3) * 4;
    const float* arow = (am < mcnt) ? (g_h + (size_t)(m0 + am) * FDIM) : nullptr;

    int bk = tid >> 4;
    int bn = (tid & 15) * 4;
    const float* wp = w2 + (size_t)e * FDIM * DIM;

    float acc[4][4];
    #pragma unroll
    for (int i = 0; i < 4; i++)
        #pragma unroll
        for (int j = 0; j < 4; j++) acc[i][j] = 0.f;

    for (int k0 = 0; k0 < FDIM; k0 += BK) {
        float4 av = make_float4(0.f, 0.f, 0.f, 0.f);
        if (arow) av = *(const float4*)(arow + k0 + ak);
        As[ak + 0][am] = av.x;
        As[ak + 1][am] = av.y;
        As[ak + 2][am] = av.z;
        As[ak + 3][am] = av.w;
        *(float4*)&Bs[bk][bn] =
            *(const float4*)(wp + (size_t)(k0 + bk) * DIM + n0 + bn);
        __syncthreads();

        #pragma unroll
        for (int k = 0; k < BK; k++) {
            float4 a = *(const float4*)&As[k][ty * 4];
            float4 b = *(const float4*)&Bs[k][tx * 4];
            acc[0][0] += a.x * b.x; acc[0][1] += a.x * b.y; acc[0][2] += a.x * b.z; acc[0][3] += a.x * b.w;
            acc[1][0] += a.y * b.x; acc[1][1] += a.y * b.y; acc[1][2] += a.y * b.z; acc[1][3] += a.y * b.w;
            acc[2][0] += a.z * b.x; acc[2][1] += a.z * b.y; acc[2][2] += a.z * b.z; acc[2][3] += a.z * b.w;
            acc[3][0] += a.w * b.x; acc[3][1] += a.w * b.y; acc[3][2] += a.w * b.z; acc[3][3] += a.w * b.w;
        }
        __syncthreads();
    }

    const float* bb = b2 + e * DIM + n0;
    #pragma unroll
    for (int i = 0; i < 4; i++) {
        int m = ty * 4 + i;
        if (m < mcnt) {
            float4 v;
            v.x = acc[i][0] + bb[tx * 4 + 0];
            v.y = acc[i][1] + bb[tx * 4 + 1];
            v.z = acc[i][2] + bb[tx * 4 + 2];
            v.w = acc[i][3] + bb[tx * 4 + 3];
            int orow = g_perm[m0 + m];
            *(float4*)(out + (size_t)orow * DIM + n0 + tx * 4) = v;
        }
    }
}

// ---------------------------------------------------------------- launch
extern "C" void kernel_launch(void* const* d_in, const int* in_sizes, int n_in,
                              void* d_out, int out_size)
{
    const float* x  = (const float*)d_in[0];
    const float* rw = (const float*)d_in[1];
    const float* rb = (const float*)d_in[2];
    const float* w1 = (const float*)d_in[3];
    const float* b1 = (const float*)d_in[4];
    const float* w2 = (const float*)d_in[5];
    const float* b2 = (const float*)d_in[6];
    float* out = (float*)d_out;

    init_kernel<<<1, 32>>>();
    router_kernel<<<T_TOK, 256>>>(x, rw, rb);
    prefix_kernel<<<1, 32>>>(out, out_size);
    scatter_kernel<<<(T_TOK + 255) / 256, 256>>>();

    dim3 g1(FDIM / BN, (T_TOK + BM - 1) / BM, NE);
    gemm1_kernel<<<g1, 256>>>(x, w1, b1);

    dim3 g2(DIM / BN, (T_TOK + BM - 1) / BM, NE);
    gemm2_kernel<<<g2, 256>>>(w2, b2, out);
}

// round 4
// speedup vs baseline: 2.7984x; 2.7984x over previous
#include <cuda_runtime.h>
#include <cuda_bf16.h>
#include <cstdint>

#define T_TOK 16384
#define DIM   1024
#define NE    8
#define FDIM  4096

#define TM 128
#define TN 128
#define TK 32
#define LDA 40          // padded bf16 K-stride in smem (conflict-free ldmatrix)
#define MAT_BYTES (128 * LDA * 2)      // 10240
#define STAGE_BYTES (4 * MAT_BYTES)    // Ah, Al, Bh, Bl = 40960
#define SMEM_SZ (2 * STAGE_BYTES)      // 81920

// ---------------- device scratch (referenced ONLY from device code) ----------------
__device__ int   g_idx[T_TOK];
__device__ int   g_counts[NE];
__device__ int   g_offsets[NE + 1];
__device__ int   g_cursor[NE];
__device__ int   g_perm[T_TOK];

__device__ __nv_bfloat16 g_xs_hi[(size_t)T_TOK * DIM];
__device__ __nv_bfloat16 g_xs_lo[(size_t)T_TOK * DIM];
__device__ __nv_bfloat16 g_w1_hi[(size_t)NE * FDIM * DIM];  // [e][n=F][k=D]
__device__ __nv_bfloat16 g_w1_lo[(size_t)NE * FDIM * DIM];
__device__ __nv_bfloat16 g_w2_hi[(size_t)NE * DIM * FDIM];  // [e][n=D][k=F]
__device__ __nv_bfloat16 g_w2_lo[(size_t)NE * DIM * FDIM];
__device__ __nv_bfloat16 g_h_hi[(size_t)T_TOK * FDIM];
__device__ __nv_bfloat16 g_h_lo[(size_t)T_TOK * FDIM];

// ---------------- helpers ----------------
__device__ __forceinline__ uint32_t smem_u32(const void* p) {
    uint32_t a;
    asm("{ .reg .u64 t; cvta.to.shared.u64 t, %1; cvt.u32.u64 %0, t; }"
        : "=r"(a) : "l"(p));
    return a;
}

__device__ __forceinline__ void bsplit(float f, __nv_bfloat16& h, __nv_bfloat16& l) {
    h = __float2bfloat16(f);
    l = __float2bfloat16(f - __bfloat162float(h));
}

__device__ __forceinline__ void ldm_x4(uint32_t* r, uint32_t addr) {
    asm volatile("ldmatrix.sync.aligned.m8n8.x4.shared.b16 {%0,%1,%2,%3}, [%4];"
                 : "=r"(r[0]), "=r"(r[1]), "=r"(r[2]), "=r"(r[3]) : "r"(addr));
}
__device__ __forceinline__ void ldm_x2(uint32_t* r, uint32_t addr) {
    asm volatile("ldmatrix.sync.aligned.m8n8.x2.shared.b16 {%0,%1}, [%2];"
                 : "=r"(r[0]), "=r"(r[1]) : "r"(addr));
}
__device__ __forceinline__ void mma_bf16(float* c, const uint32_t* a, const uint32_t* b) {
    asm volatile(
        "mma.sync.aligned.m16n8k16.row.col.f32.bf16.bf16.f32 "
        "{%0,%1,%2,%3}, {%4,%5,%6,%7}, {%8,%9}, {%0,%1,%2,%3};"
        : "+f"(c[0]), "+f"(c[1]), "+f"(c[2]), "+f"(c[3])
        : "r"(a[0]), "r"(a[1]), "r"(a[2]), "r"(a[3]), "r"(b[0]), "r"(b[1]));
}
__device__ __forceinline__ void cp16(uint32_t sa, const void* g) {
    uint64_t ga = __cvta_generic_to_global(g);
    asm volatile("cp.async.cg.shared.global [%0], [%1], 16;" :: "r"(sa), "l"(ga));
}

// ---------------- router / prefix / scatter ----------------
__global__ void init_kernel() {
    int t = threadIdx.x;
    if (t < NE) { g_counts[t] = 0; g_cursor[t] = 0; }
}

__global__ __launch_bounds__(256) void router_kernel(
    const float* __restrict__ x, const float* __restrict__ rw,
    const float* __restrict__ rb)
{
    int t = blockIdx.x;
    int w = threadIdx.x >> 5;
    int l = threadIdx.x & 31;
    const float* xr = x + (size_t)t * DIM;
    float s = 0.f;
    for (int d = l; d < DIM; d += 32)
        s += xr[d] * rw[d * NE + w];
    #pragma unroll
    for (int o = 16; o; o >>= 1)
        s += __shfl_down_sync(0xffffffffu, s, o);
    __shared__ float lg[NE];
    if (l == 0) lg[w] = s + rb[w];
    __syncthreads();
    if (threadIdx.x == 0) {
        int best = 0; float bv = lg[0];
        #pragma unroll
        for (int e = 1; e < NE; e++)
            if (lg[e] > bv) { bv = lg[e]; best = e; }
        g_idx[t] = best;
        atomicAdd(&g_counts[best], 1);
    }
}

__global__ void prefix_kernel(float* __restrict__ out, int out_size) {
    if (threadIdx.x == 0) {
        int acc = 0; float lb = 0.f;
        for (int e = 0; e < NE; e++) {
            g_offsets[e] = acc;
            acc += g_counts[e];
            float u = (float)g_counts[e] / (float)T_TOK - 1.0f / (float)NE;
            lb += u * u;
        }
        g_offsets[NE] = acc;
        lb /= (float)NE;
        if (out_size > T_TOK * DIM)
            out[(size_t)T_TOK * DIM] = lb;
    }
}

__global__ void scatter_kernel() {
    int t = blockIdx.x * blockDim.x + threadIdx.x;
    if (t < T_TOK) {
        int e = g_idx[t];
        int p = atomicAdd(&g_cursor[e], 1);
        g_perm[g_offsets[e] + p] = t;
    }
}

// ---------------- conversions ----------------
__global__ void split_x_kernel(const float* __restrict__ x) {
    size_t i = ((size_t)blockIdx.x * blockDim.x + threadIdx.x) * 4;
    if (i >= (size_t)T_TOK * DIM) return;
    int r = (int)(i / DIM), d = (int)(i % DIM);
    const float4 v = *(const float4*)(x + (size_t)g_perm[r] * DIM + d);
    __nv_bfloat16 h0,l0,h1,l1,h2,l2,h3,l3;
    bsplit(v.x,h0,l0); bsplit(v.y,h1,l1); bsplit(v.z,h2,l2); bsplit(v.w,h3,l3);
    __nv_bfloat162 t0; t0.x=h0; t0.y=h1;
    __nv_bfloat162 t1; t1.x=h2; t1.y=h3;
    __nv_bfloat162 u0; u0.x=l0; u0.y=l1;
    __nv_bfloat162 u1; u1.x=l2; u1.y=l3;
    *(__nv_bfloat162*)(g_xs_hi + i)     = t0;
    *(__nv_bfloat162*)(g_xs_hi + i + 2) = t1;
    *(__nv_bfloat162*)(g_xs_lo + i)     = u0;
    *(__nv_bfloat162*)(g_xs_lo + i + 2) = u1;
}

// transpose + split: src [SR, SC] per expert -> dst [SC, SR] bf16 hi/lo.
// Destination selected INSIDE device code (W1 flag) — never host-passed symbols.
template<int SR, int SC, bool W1>
__global__ void tsplit_kernel(const float* __restrict__ w)
{
    __shared__ float tile[32][33];
    int e = blockIdx.z;
    int c0 = blockIdx.x * 32;
    int r0 = blockIdx.y * 32;
    const float* src = w + (size_t)e * SR * SC;
    int tx = threadIdx.x, ty = threadIdx.y;
    #pragma unroll
    for (int j = 0; j < 32; j += 8)
        tile[ty + j][tx] = src[(size_t)(r0 + ty + j) * SC + (c0 + tx)];
    __syncthreads();
    __nv_bfloat16* oh = (W1 ? g_w1_hi : g_w2_hi) + (size_t)e * SR * SC;
    __nv_bfloat16* ol = (W1 ? g_w1_lo : g_w2_lo) + (size_t)e * SR * SC;
    #pragma unroll
    for (int j = 0; j < 32; j += 8) {
        float f = tile[tx][ty + j];
        __nv_bfloat16 h, l; bsplit(f, h, l);
        size_t o = (size_t)(c0 + ty + j) * SR + (r0 + tx);
        oh[o] = h; ol[o] = l;
    }
}

// ---------------- grouped bf16 mma.sync GEMM ----------------
// C[128,128] = A[128,K] * B[128,K]^T via 3-pass split precision.
// All scratch operands resolved inside device code via template flag.
template<int KTOT, bool G1>
__global__ __launch_bounds__(256) void moe_mma_kernel(
    const float* __restrict__ bias, float* __restrict__ Of)
{
    constexpr int NTOT = G1 ? FDIM : DIM;
    constexpr int NCH  = KTOT / TK;

    const __nv_bfloat16* __restrict__ Ah = G1 ? g_xs_hi : g_h_hi;
    const __nv_bfloat16* __restrict__ Al = G1 ? g_xs_lo : g_h_lo;
    const __nv_bfloat16* __restrict__ Bh = G1 ? g_w1_hi : g_w2_hi;
    const __nv_bfloat16* __restrict__ Bl = G1 ? g_w1_lo : g_w2_lo;

    int e = blockIdx.z;
    int seg0 = g_offsets[e], seg1 = g_offsets[e + 1];
    int m0 = seg0 + blockIdx.y * TM;
    if (m0 >= seg1) return;
    int mcnt = min(TM, seg1 - m0);
    int n0 = blockIdx.x * TN;

    extern __shared__ char smem[];
    uint32_t sbase = smem_u32(smem);

    int tid = threadIdx.x;
    int wid = tid >> 5, lane = tid & 31;
    int warp_m = (wid >> 2) * 64;   // 0 or 64
    int warp_n = (wid & 3) * 32;    // 0,32,64,96

    const __nv_bfloat16* Beh = Bh + (size_t)e * NTOT * KTOT;
    const __nv_bfloat16* Bel = Bl + (size_t)e * NTOT * KTOT;
    const float* be = bias + (size_t)e * NTOT;

    auto prefetch = [&](int it) {
        int b = it & 1;
        int k0 = it * TK;
        uint32_t stg = sbase + b * STAGE_BYTES;
        #pragma unroll
        for (int i = 0; i < 8; i++) {
            int c   = i * 256 + tid;          // 0..2047
            int mat = c >> 9;                 // 0:Ah 1:Al 2:Bh 3:Bl
            int rw  = (c & 511) >> 2;         // 0..127
            int sg  = c & 3;                  // 16B segment in row
            uint32_t sa = stg + mat * MAT_BYTES + (rw * LDA + sg * 8) * 2;
            const __nv_bfloat16* gp;
            if (mat < 2) {
                int gr = m0 + rw;
                if (gr > T_TOK - 1) gr = T_TOK - 1;   // clamp; never stored
                gp = (mat == 0 ? Ah : Al) + (size_t)gr * KTOT + k0 + sg * 8;
            } else {
                gp = (mat == 2 ? Beh : Bel) + (size_t)(n0 + rw) * KTOT + k0 + sg * 8;
            }
            cp16(sa, gp);
        }
        asm volatile("cp.async.commit_group;" ::: "memory");
    };

    float acc[4][4][4];
    #pragma unroll
    for (int i = 0; i < 4; i++)
        #pragma unroll
        for (int j = 0; j < 4; j++)
            #pragma unroll
            for (int q = 0; q < 4; q++) acc[i][j][q] = 0.f;

    prefetch(0);

    for (int it = 0; it < NCH; ++it) {
        if (it + 1 < NCH) {
            prefetch(it + 1);
            asm volatile("cp.async.wait_group 1;" ::: "memory");
        } else {
            asm volatile("cp.async.wait_group 0;" ::: "memory");
        }
        __syncthreads();

        uint32_t stg = sbase + (it & 1) * STAGE_BYTES;
        uint32_t sAh = stg;
        uint32_t sAl = stg + MAT_BYTES;
        uint32_t sBh = stg + 2 * MAT_BYTES;
        uint32_t sBl = stg + 3 * MAT_BYTES;

        #pragma unroll
        for (int kst = 0; kst < 2; ++kst) {
            uint32_t afh[4][4], afl[4][4], bfh[4][2], bfl[4][2];
            int acol = kst * 16 + ((lane >> 4) << 3);
            int arow_off = (lane & 15);
            #pragma unroll
            for (int mt = 0; mt < 4; ++mt) {
                int row = warp_m + mt * 16 + arow_off;
                uint32_t off = (uint32_t)(row * LDA + acol) * 2;
                ldm_x4(afh[mt], sAh + off);
                ldm_x4(afl[mt], sAl + off);
            }
            int bcol = kst * 16 + (((lane >> 3) & 1) << 3);
            int brow_off = (lane & 7);
            #pragma unroll
            for (int nt = 0; nt < 4; ++nt) {
                int row = warp_n + nt * 8 + brow_off;
                uint32_t off = (uint32_t)(row * LDA + bcol) * 2;
                ldm_x2(bfh[nt], sBh + off);
                ldm_x2(bfl[nt], sBl + off);
            }
            #pragma unroll
            for (int mt = 0; mt < 4; ++mt)
                #pragma unroll
                for (int nt = 0; nt < 4; ++nt) {
                    mma_bf16(acc[mt][nt], afh[mt], bfh[nt]);
                    mma_bf16(acc[mt][nt], afh[mt], bfl[nt]);
                    mma_bf16(acc[mt][nt], afl[mt], bfh[nt]);
                }
        }
        __syncthreads();
    }

    // ---- epilogue ----
    int rbase = warp_m + (lane >> 2);
    int cbase = n0 + warp_n + (lane & 3) * 2;
    #pragma unroll
    for (int nt = 0; nt < 4; ++nt) {
        int gc = cbase + nt * 8;
        float b0 = be[gc], b1 = be[gc + 1];
        #pragma unroll
        for (int mt = 0; mt < 4; ++mt) {
            #pragma unroll
            for (int s = 0; s < 2; ++s) {
                int lr = rbase + mt * 16 + s * 8;
                if (lr < mcnt) {
                    int gr = m0 + lr;
                    float f0 = acc[mt][nt][2 * s]     + b0;
                    float f1 = acc[mt][nt][2 * s + 1] + b1;
                    if constexpr (G1) {
                        f0 = fmaxf(f0, 0.f);
                        f1 = fmaxf(f1, 0.f);
                        __nv_bfloat16 h0, l0, h1, l1;
                        bsplit(f0, h0, l0); bsplit(f1, h1, l1);
                        __nv_bfloat162 th; th.x = h0; th.y = h1;
                        __nv_bfloat162 tl; tl.x = l0; tl.y = l1;
                        size_t o = (size_t)gr * FDIM + gc;
                        *(__nv_bfloat162*)(g_h_hi + o) = th;
                        *(__nv_bfloat162*)(g_h_lo + o) = tl;
                    } else {
                        int orow = g_perm[gr];
                        float2 v; v.x = f0; v.y = f1;
                        *(float2*)(Of + (size_t)orow * DIM + gc) = v;
                    }
                }
            }
        }
    }
}

// ---------------- launch ----------------
extern "C" void kernel_launch(void* const* d_in, const int* in_sizes, int n_in,
                              void* d_out, int out_size)
{
    const float* x  = (const float*)d_in[0];
    const float* rw = (const float*)d_in[1];
    const float* rb = (const float*)d_in[2];
    const float* w1 = (const float*)d_in[3];
    const float* b1 = (const float*)d_in[4];
    const float* w2 = (const float*)d_in[5];
    const float* b2 = (const float*)d_in[6];
    float* out = (float*)d_out;

    cudaFuncSetAttribute(moe_mma_kernel<DIM, true>,
                         cudaFuncAttributeMaxDynamicSharedMemorySize, SMEM_SZ);
    cudaFuncSetAttribute(moe_mma_kernel<FDIM, false>,
                         cudaFuncAttributeMaxDynamicSharedMemorySize, SMEM_SZ);

    init_kernel<<<1, 32>>>();
    router_kernel<<<T_TOK, 256>>>(x, rw, rb);
    prefix_kernel<<<1, 32>>>(out, out_size);
    scatter_kernel<<<(T_TOK + 255) / 256, 256>>>();

    split_x_kernel<<<(T_TOK * DIM / 4 + 255) / 256, 256>>>(x);
    tsplit_kernel<DIM, FDIM, true><<<dim3(FDIM / 32, DIM / 32, NE), dim3(32, 8)>>>(w1);
    tsplit_kernel<FDIM, DIM, false><<<dim3(DIM / 32, FDIM / 32, NE), dim3(32, 8)>>>(w2);

    moe_mma_kernel<DIM, true><<<dim3(FDIM / TN, T_TOK / TM, NE), 256, SMEM_SZ>>>(b1, nullptr);
    moe_mma_kernel<FDIM, false><<<dim3(DIM / TN, T_TOK / TM, NE), 256, SMEM_SZ>>>(b2, out);
}

// round 5
// speedup vs baseline: 3.2252x; 1.1526x over previous
#include <cuda_runtime.h>
#include <cuda_fp16.h>
#include <cstdint>

#define T_TOK 16384
#define DIM   1024
#define NE    8
#define FDIM  4096

#define TM 128
#define TN 128
#define TK 32
#define LDA 40          // padded fp16 K-stride in smem (conflict-free ldmatrix)
#define MAT_BYTES (128 * LDA * 2)      // 10240
#define STAGE_BYTES (3 * MAT_BYTES)    // Ah, Al, Bh = 30720
#define NSTAGE 4
#define SMEM_SZ (NSTAGE * STAGE_BYTES) // 122880

// ---------------- device scratch (referenced ONLY from device code) ----------------
__device__ int   g_idx[T_TOK];
__device__ int   g_counts[NE];
__device__ int   g_offsets[NE + 1];
__device__ int   g_cursor[NE];
__device__ int   g_perm[T_TOK];

__device__ __half g_xs_hi[(size_t)T_TOK * DIM];
__device__ __half g_xs_lo[(size_t)T_TOK * DIM];
__device__ __half g_w1_h[(size_t)NE * FDIM * DIM];  // [e][n=F][k=D]
__device__ __half g_w2_h[(size_t)NE * DIM * FDIM];  // [e][n=D][k=F]
__device__ __half g_h_hi[(size_t)T_TOK * FDIM];
__device__ __half g_h_lo[(size_t)T_TOK * FDIM];

// ---------------- helpers ----------------
__device__ __forceinline__ uint32_t smem_u32(const void* p) {
    uint32_t a;
    asm("{ .reg .u64 t; cvta.to.shared.u64 t, %1; cvt.u32.u64 %0, t; }"
        : "=r"(a) : "l"(p));
    return a;
}

__device__ __forceinline__ void hsplit(float f, __half& h, __half& l) {
    h = __float2half(f);
    l = __float2half(f - __half2float(h));
}

__device__ __forceinline__ void ldm_x4(uint32_t* r, uint32_t addr) {
    asm volatile("ldmatrix.sync.aligned.m8n8.x4.shared.b16 {%0,%1,%2,%3}, [%4];"
                 : "=r"(r[0]), "=r"(r[1]), "=r"(r[2]), "=r"(r[3]) : "r"(addr));
}
__device__ __forceinline__ void ldm_x2(uint32_t* r, uint32_t addr) {
    asm volatile("ldmatrix.sync.aligned.m8n8.x2.shared.b16 {%0,%1}, [%2];"
                 : "=r"(r[0]), "=r"(r[1]) : "r"(addr));
}
__device__ __forceinline__ void mma_f16(float* c, const uint32_t* a, const uint32_t* b) {
    asm volatile(
        "mma.sync.aligned.m16n8k16.row.col.f32.f16.f16.f32 "
        "{%0,%1,%2,%3}, {%4,%5,%6,%7}, {%8,%9}, {%0,%1,%2,%3};"
        : "+f"(c[0]), "+f"(c[1]), "+f"(c[2]), "+f"(c[3])
        : "r"(a[0]), "r"(a[1]), "r"(a[2]), "r"(a[3]), "r"(b[0]), "r"(b[1]));
}
__device__ __forceinline__ void cp16(uint32_t sa, const void* g) {
    uint64_t ga = __cvta_generic_to_global(g);
    asm volatile("cp.async.cg.shared.global [%0], [%1], 16;" :: "r"(sa), "l"(ga));
}

// ---------------- router / prefix / scatter ----------------
__global__ void init_kernel() {
    int t = threadIdx.x;
    if (t < NE) { g_counts[t] = 0; g_cursor[t] = 0; }
}

__global__ __launch_bounds__(256) void router_kernel(
    const float* __restrict__ x, const float* __restrict__ rw,
    const float* __restrict__ rb)
{
    int t = blockIdx.x;
    int w = threadIdx.x >> 5;
    int l = threadIdx.x & 31;
    const float* xr = x + (size_t)t * DIM;
    float s = 0.f;
    for (int d = l; d < DIM; d += 32)
        s += xr[d] * rw[d * NE + w];
    #pragma unroll
    for (int o = 16; o; o >>= 1)
        s += __shfl_down_sync(0xffffffffu, s, o);
    __shared__ float lg[NE];
    if (l == 0) lg[w] = s + rb[w];
    __syncthreads();
    if (threadIdx.x == 0) {
        int best = 0; float bv = lg[0];
        #pragma unroll
        for (int e = 1; e < NE; e++)
            if (lg[e] > bv) { bv = lg[e]; best = e; }
        g_idx[t] = best;
        atomicAdd(&g_counts[best], 1);
    }
}

__global__ void prefix_kernel(float* __restrict__ out, int out_size) {
    if (threadIdx.x == 0) {
        int acc = 0; float lb = 0.f;
        for (int e = 0; e < NE; e++) {
            g_offsets[e] = acc;
            acc += g_counts[e];
            float u = (float)g_counts[e] / (float)T_TOK - 1.0f / (float)NE;
            lb += u * u;
        }
        g_offsets[NE] = acc;
        lb /= (float)NE;
        if (out_size > T_TOK * DIM)
            out[(size_t)T_TOK * DIM] = lb;
    }
}

__global__ void scatter_kernel() {
    int t = blockIdx.x * blockDim.x + threadIdx.x;
    if (t < T_TOK) {
        int e = g_idx[t];
        int p = atomicAdd(&g_cursor[e], 1);
        g_perm[g_offsets[e] + p] = t;
    }
}

// ---------------- conversions ----------------
__global__ void split_x_kernel(const float* __restrict__ x) {
    size_t i = ((size_t)blockIdx.x * blockDim.x + threadIdx.x) * 4;
    if (i >= (size_t)T_TOK * DIM) return;
    int r = (int)(i / DIM), d = (int)(i % DIM);
    const float4 v = *(const float4*)(x + (size_t)g_perm[r] * DIM + d);
    __half h0,l0,h1,l1,h2,l2,h3,l3;
    hsplit(v.x,h0,l0); hsplit(v.y,h1,l1); hsplit(v.z,h2,l2); hsplit(v.w,h3,l3);
    __half2 t0; t0.x=h0; t0.y=h1;
    __half2 t1; t1.x=h2; t1.y=h3;
    __half2 u0; u0.x=l0; u0.y=l1;
    __half2 u1; u1.x=l2; u1.y=l3;
    *(__half2*)(g_xs_hi + i)     = t0;
    *(__half2*)(g_xs_hi + i + 2) = t1;
    *(__half2*)(g_xs_lo + i)     = u0;
    *(__half2*)(g_xs_lo + i + 2) = u1;
}

// transpose + round to fp16: src [SR, SC] per expert -> dst [SC, SR]
template<int SR, int SC, bool W1>
__global__ void tsplit_kernel(const float* __restrict__ w)
{
    __shared__ float tile[32][33];
    int e = blockIdx.z;
    int c0 = blockIdx.x * 32;
    int r0 = blockIdx.y * 32;
    const float* src = w + (size_t)e * SR * SC;
    int tx = threadIdx.x, ty = threadIdx.y;
    #pragma unroll
    for (int j = 0; j < 32; j += 8)
        tile[ty + j][tx] = src[(size_t)(r0 + ty + j) * SC + (c0 + tx)];
    __syncthreads();
    __half* oh = (W1 ? g_w1_h : g_w2_h) + (size_t)e * SR * SC;
    #pragma unroll
    for (int j = 0; j < 32; j += 8) {
        float f = tile[tx][ty + j];
        size_t o = (size_t)(c0 + ty + j) * SR + (r0 + tx);
        oh[o] = __float2half(f);
    }
}

// ---------------- grouped fp16 mma.sync GEMM ----------------
// C[128,128] = (Ah+Al)[128,K] * Bh[128,K]^T  (2-pass fp16 split precision)
template<int KTOT, bool G1>
__global__ __launch_bounds__(256) void moe_mma_kernel(
    const float* __restrict__ bias, float* __restrict__ Of)
{
    constexpr int NTOT = G1 ? FDIM : DIM;
    constexpr int NCH  = KTOT / TK;

    const __half* __restrict__ Ah = G1 ? g_xs_hi : g_h_hi;
    const __half* __restrict__ Al = G1 ? g_xs_lo : g_h_lo;
    const __half* __restrict__ Bh = G1 ? g_w1_h : g_w2_h;

    int e = blockIdx.z;
    int seg0 = g_offsets[e], seg1 = g_offsets[e + 1];
    int m0 = seg0 + blockIdx.y * TM;
    if (m0 >= seg1) return;
    int mcnt = min(TM, seg1 - m0);
    int n0 = blockIdx.x * TN;

    extern __shared__ char smem[];
    uint32_t sbase = smem_u32(smem);

    int tid = threadIdx.x;
    int wid = tid >> 5, lane = tid & 31;
    int warp_m = (wid >> 2) * 64;   // 0 or 64
    int warp_n = (wid & 3) * 32;    // 0,32,64,96

    const __half* Beh = Bh + (size_t)e * NTOT * KTOT;
    const float* be = bias + (size_t)e * NTOT;

    auto prefetch = [&](int it) {
        if (it < NCH) {
            int k0 = it * TK;
            uint32_t stg = sbase + (uint32_t)(it & (NSTAGE - 1)) * STAGE_BYTES;
            #pragma unroll
            for (int i = 0; i < 6; i++) {
                int c   = i * 256 + tid;          // 0..1535
                int mat = c >> 9;                 // 0:Ah 1:Al 2:Bh
                int rw  = (c & 511) >> 2;         // 0..127
                int sg  = c & 3;                  // 16B segment in row
                uint32_t sa = stg + mat * MAT_BYTES + (rw * LDA + sg * 8) * 2;
                const __half* gp;
                if (mat < 2) {
                    int gr = m0 + rw;
                    if (gr > T_TOK - 1) gr = T_TOK - 1;   // clamp; never stored
                    gp = (mat == 0 ? Ah : Al) + (size_t)gr * KTOT + k0 + sg * 8;
                } else {
                    gp = Beh + (size_t)(n0 + rw) * KTOT + k0 + sg * 8;
                }
                cp16(sa, gp);
            }
        }
        asm volatile("cp.async.commit_group;" ::: "memory");
    };

    float acc[4][4][4];
    #pragma unroll
    for (int i = 0; i < 4; i++)
        #pragma unroll
        for (int j = 0; j < 4; j++)
            #pragma unroll
            for (int q = 0; q < 4; q++) acc[i][j][q] = 0.f;

    prefetch(0);
    prefetch(1);
    prefetch(2);

    for (int it = 0; it < NCH; ++it) {
        prefetch(it + 3);
        asm volatile("cp.async.wait_group 3;" ::: "memory");
        __syncthreads();   // stage `it` visible to all warps

        uint32_t stg = sbase + (uint32_t)(it & (NSTAGE - 1)) * STAGE_BYTES;
        uint32_t sAh = stg;
        uint32_t sAl = stg + MAT_BYTES;
        uint32_t sBh = stg + 2 * MAT_BYTES;

        #pragma unroll
        for (int kst = 0; kst < 2; ++kst) {
            uint32_t afh[4][4], afl[4][4], bfh[4][2];
            int acol = kst * 16 + ((lane >> 4) << 3);
            int arow_off = (lane & 15);
            #pragma unroll
            for (int mt = 0; mt < 4; ++mt) {
                int row = warp_m + mt * 16 + arow_off;
                uint32_t off = (uint32_t)(row * LDA + acol) * 2;
                ldm_x4(afh[mt], sAh + off);
                ldm_x4(afl[mt], sAl + off);
            }
            int bcol = kst * 16 + (((lane >> 3) & 1) << 3);
            int brow_off = (lane & 7);
            #pragma unroll
            for (int nt = 0; nt < 4; ++nt) {
                int row = warp_n + nt * 8 + brow_off;
                uint32_t off = (uint32_t)(row * LDA + bcol) * 2;
                ldm_x2(bfh[nt], sBh + off);
            }
            #pragma unroll
            for (int mt = 0; mt < 4; ++mt)
                #pragma unroll
                for (int nt = 0; nt < 4; ++nt) {
                    mma_f16(acc[mt][nt], afh[mt], bfh[nt]);
                    mma_f16(acc[mt][nt], afl[mt], bfh[nt]);
                }
        }
        __syncthreads();   // all warps done reading stage before it is re-filled
    }

    // ---- epilogue ----
    int rbase = warp_m + (lane >> 2);
    int cbase = n0 + warp_n + (lane & 3) * 2;
    #pragma unroll
    for (int nt = 0; nt < 4; ++nt) {
        int gc = cbase + nt * 8;
        float b0 = be[gc], b1 = be[gc + 1];
        #pragma unroll
        for (int mt = 0; mt < 4; ++mt) {
            #pragma unroll
            for (int s = 0; s < 2; ++s) {
                int lr = rbase + mt * 16 + s * 8;
                if (lr < mcnt) {
                    int gr = m0 + lr;
                    float f0 = acc[mt][nt][2 * s]     + b0;
                    float f1 = acc[mt][nt][2 * s + 1] + b1;
                    if constexpr (G1) {
                        f0 = fmaxf(f0, 0.f);
                        f1 = fmaxf(f1, 0.f);
                        __half h0, l0, h1, l1;
                        hsplit(f0, h0, l0); hsplit(f1, h1, l1);
                        __half2 th; th.x = h0; th.y = h1;
                        __half2 tl; tl.x = l0; tl.y = l1;
                        size_t o = (size_t)gr * FDIM + gc;
                        *(__half2*)(g_h_hi + o) = th;
                        *(__half2*)(g_h_lo + o) = tl;
                    } else {
                        int orow = g_perm[gr];
                        float2 v; v.x = f0; v.y = f1;
                        *(float2*)(Of + (size_t)orow * DIM + gc) = v;
                    }
                }
            }
        }
    }
}

// ---------------- launch ----------------
extern "C" void kernel_launch(void* const* d_in, const int* in_sizes, int n_in,
                              void* d_out, int out_size)
{
    const float* x  = (const float*)d_in[0];
    const float* rw = (const float*)d_in[1];
    const float* rb = (const float*)d_in[2];
    const float* w1 = (const float*)d_in[3];
    const float* b1 = (const float*)d_in[4];
    const float* w2 = (const float*)d_in[5];
    const float* b2 = (const float*)d_in[6];
    float* out = (float*)d_out;

    cudaFuncSetAttribute(moe_mma_kernel<DIM, true>,
                         cudaFuncAttributeMaxDynamicSharedMemorySize, SMEM_SZ);
    cudaFuncSetAttribute(moe_mma_kernel<FDIM, false>,
                         cudaFuncAttributeMaxDynamicSharedMemorySize, SMEM_SZ);

    init_kernel<<<1, 32>>>();
    router_kernel<<<T_TOK, 256>>>(x, rw, rb);
    prefix_kernel<<<1, 32>>>(out, out_size);
    scatter_kernel<<<(T_TOK + 255) / 256, 256>>>();

    split_x_kernel<<<(T_TOK * DIM / 4 + 255) / 256, 256>>>(x);
    tsplit_kernel<DIM, FDIM, true><<<dim3(FDIM / 32, DIM / 32, NE), dim3(32, 8)>>>(w1);
    tsplit_kernel<FDIM, DIM, false><<<dim3(DIM / 32, FDIM / 32, NE), dim3(32, 8)>>>(w2);

    moe_mma_kernel<DIM, true><<<dim3(FDIM / TN, T_TOK / TM, NE), 256, SMEM_SZ>>>(b1, nullptr);
    moe_mma_kernel<FDIM, false><<<dim3(DIM / TN, T_TOK / TM, NE), 256, SMEM_SZ>>>(b2, out);
}

// round 6
// speedup vs baseline: 3.8317x; 1.1880x over previous
#include <cuda_runtime.h>
#include <cuda_fp16.h>
#include <cstdint>

#define T_TOK 16384
#define DIM   1024
#define NE    8
#define FDIM  4096

#define TM 128
#define TN 128
#define TK 32
#define LDA 40          // padded fp16 K-stride in smem (conflict-free ldmatrix)
#define MAT_BYTES (128 * LDA * 2)      // 10240
#define STAGE_BYTES (3 * MAT_BYTES)    // Ah, Al, Bh = 30720
#define NSTAGE 3
#define SMEM_SZ (NSTAGE * STAGE_BYTES) // 92160 -> 2 CTAs/SM

// ---------------- device scratch (referenced ONLY from device code) ----------------
__device__ int   g_idx[T_TOK];
__device__ int   g_counts[NE];
__device__ int   g_offsets[NE + 1];
__device__ int   g_cursor[NE];
__device__ int   g_perm[T_TOK];

__device__ __half g_xs_hi[(size_t)T_TOK * DIM];
__device__ __half g_xs_lo[(size_t)T_TOK * DIM];
__device__ __half g_w1_h[(size_t)NE * FDIM * DIM];  // [e][n=F][k=D]
__device__ __half g_w2_h[(size_t)NE * DIM * FDIM];  // [e][n=D][k=F]
__device__ __half g_h_hi[(size_t)T_TOK * FDIM];
__device__ __half g_h_lo[(size_t)T_TOK * FDIM];

// ---------------- helpers ----------------
__device__ __forceinline__ uint32_t smem_u32(const void* p) {
    uint32_t a;
    asm("{ .reg .u64 t; cvta.to.shared.u64 t, %1; cvt.u32.u64 %0, t; }"
        : "=r"(a) : "l"(p));
    return a;
}

__device__ __forceinline__ void hsplit(float f, __half& h, __half& l) {
    h = __float2half(f);
    l = __float2half(f - __half2float(h));
}

__device__ __forceinline__ void ldm_x4(uint32_t* r, uint32_t addr) {
    asm volatile("ldmatrix.sync.aligned.m8n8.x4.shared.b16 {%0,%1,%2,%3}, [%4];"
                 : "=r"(r[0]), "=r"(r[1]), "=r"(r[2]), "=r"(r[3]) : "r"(addr));
}
__device__ __forceinline__ void ldm_x2(uint32_t* r, uint32_t addr) {
    asm volatile("ldmatrix.sync.aligned.m8n8.x2.shared.b16 {%0,%1}, [%2];"
                 : "=r"(r[0]), "=r"(r[1]) : "r"(addr));
}
__device__ __forceinline__ void mma_f16(float* c, const uint32_t* a, const uint32_t* b) {
    asm volatile(
        "mma.sync.aligned.m16n8k16.row.col.f32.f16.f16.f32 "
        "{%0,%1,%2,%3}, {%4,%5,%6,%7}, {%8,%9}, {%0,%1,%2,%3};"
        : "+f"(c[0]), "+f"(c[1]), "+f"(c[2]), "+f"(c[3])
        : "r"(a[0]), "r"(a[1]), "r"(a[2]), "r"(a[3]), "r"(b[0]), "r"(b[1]));
}
__device__ __forceinline__ void cp16(uint32_t sa, const void* g) {
    uint64_t ga = __cvta_generic_to_global(g);
    asm volatile("cp.async.cg.shared.global [%0], [%1], 16;" :: "r"(sa), "l"(ga));
}

// ---------------- router / prefix / scatter ----------------
__global__ void init_kernel() {
    int t = threadIdx.x;
    if (t < NE) { g_counts[t] = 0; g_cursor[t] = 0; }
}

__global__ __launch_bounds__(256) void router_kernel(
    const float* __restrict__ x, const float* __restrict__ rw,
    const float* __restrict__ rb)
{
    int t = blockIdx.x;
    int w = threadIdx.x >> 5;
    int l = threadIdx.x & 31;
    const float* xr = x + (size_t)t * DIM;
    float s = 0.f;
    for (int d = l; d < DIM; d += 32)
        s += xr[d] * rw[d * NE + w];
    #pragma unroll
    for (int o = 16; o; o >>= 1)
        s += __shfl_down_sync(0xffffffffu, s, o);
    __shared__ float lg[NE];
    if (l == 0) lg[w] = s + rb[w];
    __syncthreads();
    if (threadIdx.x == 0) {
        int best = 0; float bv = lg[0];
        #pragma unroll
        for (int e = 1; e < NE; e++)
            if (lg[e] > bv) { bv = lg[e]; best = e; }
        g_idx[t] = best;
        atomicAdd(&g_counts[best], 1);
    }
}

__global__ void prefix_kernel(float* __restrict__ out, int out_size) {
    if (threadIdx.x == 0) {
        int acc = 0; float lb = 0.f;
        for (int e = 0; e < NE; e++) {
            g_offsets[e] = acc;
            acc += g_counts[e];
            float u = (float)g_counts[e] / (float)T_TOK - 1.0f / (float)NE;
            lb += u * u;
        }
        g_offsets[NE] = acc;
        lb /= (float)NE;
        if (out_size > T_TOK * DIM)
            out[(size_t)T_TOK * DIM] = lb;
    }
}

__global__ void scatter_kernel() {
    int t = blockIdx.x * blockDim.x + threadIdx.x;
    if (t < T_TOK) {
        int e = g_idx[t];
        int p = atomicAdd(&g_cursor[e], 1);
        g_perm[g_offsets[e] + p] = t;
    }
}

// ---------------- conversions ----------------
__global__ void split_x_kernel(const float* __restrict__ x) {
    size_t i = ((size_t)blockIdx.x * blockDim.x + threadIdx.x) * 4;
    if (i >= (size_t)T_TOK * DIM) return;
    int r = (int)(i / DIM), d = (int)(i % DIM);
    const float4 v = *(const float4*)(x + (size_t)g_perm[r] * DIM + d);
    __half h0,l0,h1,l1,h2,l2,h3,l3;
    hsplit(v.x,h0,l0); hsplit(v.y,h1,l1); hsplit(v.z,h2,l2); hsplit(v.w,h3,l3);
    __half2 t0; t0.x=h0; t0.y=h1;
    __half2 t1; t1.x=h2; t1.y=h3;
    __half2 u0; u0.x=l0; u0.y=l1;
    __half2 u1; u1.x=l2; u1.y=l3;
    *(__half2*)(g_xs_hi + i)     = t0;
    *(__half2*)(g_xs_hi + i + 2) = t1;
    *(__half2*)(g_xs_lo + i)     = u0;
    *(__half2*)(g_xs_lo + i + 2) = u1;
}

// transpose + round to fp16: src [SR, SC] per expert -> dst [SC, SR]
template<int SR, int SC, bool W1>
__global__ void tsplit_kernel(const float* __restrict__ w)
{
    __shared__ float tile[32][33];
    int e = blockIdx.z;
    int c0 = blockIdx.x * 32;
    int r0 = blockIdx.y * 32;
    const float* src = w + (size_t)e * SR * SC;
    int tx = threadIdx.x, ty = threadIdx.y;
    #pragma unroll
    for (int j = 0; j < 32; j += 8)
        tile[ty + j][tx] = src[(size_t)(r0 + ty + j) * SC + (c0 + tx)];
    __syncthreads();
    __half* oh = (W1 ? g_w1_h : g_w2_h) + (size_t)e * SR * SC;
    #pragma unroll
    for (int j = 0; j < 32; j += 8) {
        float f = tile[tx][ty + j];
        size_t o = (size_t)(c0 + ty + j) * SR + (r0 + tx);
        oh[o] = __float2half(f);
    }
}

// ---------------- grouped fp16 mma.sync GEMM ----------------
// C[128,128] = (Ah+Al)[128,K] * Bh[128,K]^T  (2-pass fp16 split precision)
template<int KTOT, bool G1>
__global__ __launch_bounds__(256, 2) void moe_mma_kernel(
    const float* __restrict__ bias, float* __restrict__ Of)
{
    constexpr int NTOT = G1 ? FDIM : DIM;
    constexpr int NCH  = KTOT / TK;

    const __half* __restrict__ Ah = G1 ? g_xs_hi : g_h_hi;
    const __half* __restrict__ Al = G1 ? g_xs_lo : g_h_lo;
    const __half* __restrict__ Bh = G1 ? g_w1_h : g_w2_h;

    int e = blockIdx.z;
    int seg0 = g_offsets[e], seg1 = g_offsets[e + 1];
    int m0 = seg0 + blockIdx.y * TM;
    if (m0 >= seg1) return;
    int mcnt = min(TM, seg1 - m0);
    int n0 = blockIdx.x * TN;

    extern __shared__ char smem[];
    uint32_t sbase = smem_u32(smem);

    int tid = threadIdx.x;
    int wid = tid >> 5, lane = tid & 31;
    int warp_m = (wid >> 2) * 64;   // 0 or 64
    int warp_n = (wid & 3) * 32;    // 0,32,64,96

    const __half* Beh = Bh + (size_t)e * NTOT * KTOT;
    const float* be = bias + (size_t)e * NTOT;

    auto prefetch = [&](int it) {
        if (it < NCH) {
            int k0 = it * TK;
            uint32_t stg = sbase + (uint32_t)(it % NSTAGE) * STAGE_BYTES;
            #pragma unroll
            for (int i = 0; i < 6; i++) {
                int c   = i * 256 + tid;          // 0..1535
                int mat = c >> 9;                 // 0:Ah 1:Al 2:Bh
                int rw  = (c & 511) >> 2;         // 0..127
                int sg  = c & 3;                  // 16B segment in row
                uint32_t sa = stg + mat * MAT_BYTES + (rw * LDA + sg * 8) * 2;
                const __half* gp;
                if (mat < 2) {
                    int gr = m0 + rw;
                    if (gr > T_TOK - 1) gr = T_TOK - 1;   // clamp; never stored
                    gp = (mat == 0 ? Ah : Al) + (size_t)gr * KTOT + k0 + sg * 8;
                } else {
                    gp = Beh + (size_t)(n0 + rw) * KTOT + k0 + sg * 8;
                }
                cp16(sa, gp);
            }
        }
        asm volatile("cp.async.commit_group;" ::: "memory");
    };

    float acc[4][4][4];
    #pragma unroll
    for (int i = 0; i < 4; i++)
        #pragma unroll
        for (int j = 0; j < 4; j++)
            #pragma unroll
            for (int q = 0; q < 4; q++) acc[i][j][q] = 0.f;

    prefetch(0);
    prefetch(1);

    for (int it = 0; it < NCH; ++it) {
        asm volatile("cp.async.wait_group 1;" ::: "memory");
        __syncthreads();        // stage `it` visible; stage (it-1) reads all done
        prefetch(it + 2);       // overwrites stage (it+2)%3 == (it-1)%3 -- safe

        uint32_t stg = sbase + (uint32_t)(it % NSTAGE) * STAGE_BYTES;
        uint32_t sAh = stg;
        uint32_t sAl = stg + MAT_BYTES;
        uint32_t sBh = stg + 2 * MAT_BYTES;

        #pragma unroll
        for (int kst = 0; kst < 2; ++kst) {
            uint32_t afh[4][4], afl[4][4], bfh[4][2];
            int acol = kst * 16 + ((lane >> 4) << 3);
            int arow_off = (lane & 15);
            #pragma unroll
            for (int mt = 0; mt < 4; ++mt) {
                int row = warp_m + mt * 16 + arow_off;
                uint32_t off = (uint32_t)(row * LDA + acol) * 2;
                ldm_x4(afh[mt], sAh + off);
                ldm_x4(afl[mt], sAl + off);
            }
            int bcol = kst * 16 + (((lane >> 3) & 1) << 3);
            int brow_off = (lane & 7);
            #pragma unroll
            for (int nt = 0; nt < 4; ++nt) {
                int row = warp_n + nt * 8 + brow_off;
                uint32_t off = (uint32_t)(row * LDA + bcol) * 2;
                ldm_x2(bfh[nt], sBh + off);
            }
            #pragma unroll
            for (int mt = 0; mt < 4; ++mt)
                #pragma unroll
                for (int nt = 0; nt < 4; ++nt) {
                    mma_f16(acc[mt][nt], afh[mt], bfh[nt]);
                    mma_f16(acc[mt][nt], afl[mt], bfh[nt]);
                }
        }
    }

    // ---- epilogue ----
    int rbase = warp_m + (lane >> 2);
    int cbase = n0 + warp_n + (lane & 3) * 2;
    #pragma unroll
    for (int nt = 0; nt < 4; ++nt) {
        int gc = cbase + nt * 8;
        float b0 = be[gc], b1 = be[gc + 1];
        #pragma unroll
        for (int mt = 0; mt < 4; ++mt) {
            #pragma unroll
            for (int s = 0; s < 2; ++s) {
                int lr = rbase + mt * 16 + s * 8;
                if (lr < mcnt) {
                    int gr = m0 + lr;
                    float f0 = acc[mt][nt][2 * s]     + b0;
                    float f1 = acc[mt][nt][2 * s + 1] + b1;
                    if constexpr (G1) {
                        f0 = fmaxf(f0, 0.f);
                        f1 = fmaxf(f1, 0.f);
                        __half h0, l0, h1, l1;
                        hsplit(f0, h0, l0); hsplit(f1, h1, l1);
                        __half2 th; th.x = h0; th.y = h1;
                        __half2 tl; tl.x = l0; tl.y = l1;
                        size_t o = (size_t)gr * FDIM + gc;
                        *(__half2*)(g_h_hi + o) = th;
                        *(__half2*)(g_h_lo + o) = tl;
                    } else {
                        int orow = g_perm[gr];
                        float2 v; v.x = f0; v.y = f1;
                        *(float2*)(Of + (size_t)orow * DIM + gc) = v;
                    }
                }
            }
        }
    }
}

// ---------------- launch ----------------
extern "C" void kernel_launch(void* const* d_in, const int* in_sizes, int n_in,
                              void* d_out, int out_size)
{
    const float* x  = (const float*)d_in[0];
    const float* rw = (const float*)d_in[1];
    const float* rb = (const float*)d_in[2];
    const float* w1 = (const float*)d_in[3];
    const float* b1 = (const float*)d_in[4];
    const float* w2 = (const float*)d_in[5];
    const float* b2 = (const float*)d_in[6];
    float* out = (float*)d_out;

    cudaFuncSetAttribute(moe_mma_kernel<DIM, true>,
                         cudaFuncAttributeMaxDynamicSharedMemorySize, SMEM_SZ);
    cudaFuncSetAttribute(moe_mma_kernel<FDIM, false>,
                         cudaFuncAttributeMaxDynamicSharedMemorySize, SMEM_SZ);

    init_kernel<<<1, 32>>>();
    router_kernel<<<T_TOK, 256>>>(x, rw, rb);
    prefix_kernel<<<1, 32>>>(out, out_size);
    scatter_kernel<<<(T_TOK + 255) / 256, 256>>>();

    split_x_kernel<<<(T_TOK * DIM / 4 + 255) / 256, 256>>>(x);
    tsplit_kernel<DIM, FDIM, true><<<dim3(FDIM / 32, DIM / 32, NE), dim3(32, 8)>>>(w1);
    tsplit_kernel<FDIM, DIM, false><<<dim3(DIM / 32, FDIM / 32, NE), dim3(32, 8)>>>(w2);

    moe_mma_kernel<DIM, true><<<dim3(FDIM / TN, T_TOK / TM, NE), 256, SMEM_SZ>>>(b1, nullptr);
    moe_mma_kernel<FDIM, false><<<dim3(DIM / TN, T_TOK / TM, NE), 256, SMEM_SZ>>>(b2, out);
}

// round 7
// speedup vs baseline: 6.0875x; 1.5887x over previous
#include <cuda_runtime.h>
#include <cuda_fp16.h>
#include <cstdint>

#define T_TOK 16384
#define DIM   1024
#define NE    8
#define FDIM  4096

#define TM 128
#define TN 128
#define TK 32
#define LDA 40          // padded fp16 K-stride in smem (conflict-free ldmatrix)
#define MAT_BYTES (128 * LDA * 2)      // 10240
#define STAGE_BYTES (2 * MAT_BYTES)    // Ah, Bh = 20480
#define NSTAGE 4
#define SMEM_SZ (NSTAGE * STAGE_BYTES) // 81920 -> 2 CTAs/SM

// ---------------- device scratch (referenced ONLY from device code) ----------------
__device__ int   g_idx[T_TOK];
__device__ int   g_counts[NE];
__device__ int   g_offsets[NE + 1];
__device__ int   g_cursor[NE];
__device__ int   g_perm[T_TOK];

__device__ __half g_xs[(size_t)T_TOK * DIM];        // gathered x, fp16
__device__ __half g_w1_h[(size_t)NE * FDIM * DIM];  // [e][n=F][k=D]
__device__ __half g_w2_h[(size_t)NE * DIM * FDIM];  // [e][n=D][k=F]
__device__ __half g_h[(size_t)T_TOK * FDIM];        // hidden, fp16

// ---------------- helpers ----------------
__device__ __forceinline__ uint32_t smem_u32(const void* p) {
    uint32_t a;
    asm("{ .reg .u64 t; cvta.to.shared.u64 t, %1; cvt.u32.u64 %0, t; }"
        : "=r"(a) : "l"(p));
    return a;
}

__device__ __forceinline__ void ldm_x4(uint32_t* r, uint32_t addr) {
    asm volatile("ldmatrix.sync.aligned.m8n8.x4.shared.b16 {%0,%1,%2,%3}, [%4];"
                 : "=r"(r[0]), "=r"(r[1]), "=r"(r[2]), "=r"(r[3]) : "r"(addr));
}
__device__ __forceinline__ void ldm_x2(uint32_t* r, uint32_t addr) {
    asm volatile("ldmatrix.sync.aligned.m8n8.x2.shared.b16 {%0,%1}, [%2];"
                 : "=r"(r[0]), "=r"(r[1]) : "r"(addr));
}
__device__ __forceinline__ void mma_f16(float* c, const uint32_t* a, const uint32_t* b) {
    asm volatile(
        "mma.sync.aligned.m16n8k16.row.col.f32.f16.f16.f32 "
        "{%0,%1,%2,%3}, {%4,%5,%6,%7}, {%8,%9}, {%0,%1,%2,%3};"
        : "+f"(c[0]), "+f"(c[1]), "+f"(c[2]), "+f"(c[3])
        : "r"(a[0]), "r"(a[1]), "r"(a[2]), "r"(a[3]), "r"(b[0]), "r"(b[1]));
}
__device__ __forceinline__ void cp16(uint32_t sa, const void* g) {
    uint64_t ga = __cvta_generic_to_global(g);
    asm volatile("cp.async.cg.shared.global [%0], [%1], 16;" :: "r"(sa), "l"(ga));
}

// ---------------- router / prefix / scatter ----------------
__global__ void init_kernel() {
    int t = threadIdx.x;
    if (t < NE) { g_counts[t] = 0; g_cursor[t] = 0; }
}

__global__ __launch_bounds__(256) void router_kernel(
    const float* __restrict__ x, const float* __restrict__ rw,
    const float* __restrict__ rb)
{
    int t = blockIdx.x;
    int w = threadIdx.x >> 5;
    int l = threadIdx.x & 31;
    const float* xr = x + (size_t)t * DIM;
    float s = 0.f;
    for (int d = l; d < DIM; d += 32)
        s += xr[d] * rw[d * NE + w];
    #pragma unroll
    for (int o = 16; o; o >>= 1)
        s += __shfl_down_sync(0xffffffffu, s, o);
    __shared__ float lg[NE];
    if (l == 0) lg[w] = s + rb[w];
    __syncthreads();
    if (threadIdx.x == 0) {
        int best = 0; float bv = lg[0];
        #pragma unroll
        for (int e = 1; e < NE; e++)
            if (lg[e] > bv) { bv = lg[e]; best = e; }
        g_idx[t] = best;
        atomicAdd(&g_counts[best], 1);
    }
}

__global__ void prefix_kernel(float* __restrict__ out, int out_size) {
    if (threadIdx.x == 0) {
        int acc = 0; float lb = 0.f;
        for (int e = 0; e < NE; e++) {
            g_offsets[e] = acc;
            acc += g_counts[e];
            float u = (float)g_counts[e] / (float)T_TOK - 1.0f / (float)NE;
            lb += u * u;
        }
        g_offsets[NE] = acc;
        lb /= (float)NE;
        if (out_size > T_TOK * DIM)
            out[(size_t)T_TOK * DIM] = lb;
    }
}

__global__ void scatter_kernel() {
    int t = blockIdx.x * blockDim.x + threadIdx.x;
    if (t < T_TOK) {
        int e = g_idx[t];
        int p = atomicAdd(&g_cursor[e], 1);
        g_perm[g_offsets[e] + p] = t;
    }
}

// ---------------- conversions ----------------
// x gathered by perm -> fp16 (permuted row order)
__global__ void cvt_x_kernel(const float* __restrict__ x) {
    size_t i = ((size_t)blockIdx.x * blockDim.x + threadIdx.x) * 4;
    if (i >= (size_t)T_TOK * DIM) return;
    int r = (int)(i / DIM), d = (int)(i % DIM);
    const float4 v = *(const float4*)(x + (size_t)g_perm[r] * DIM + d);
    __half2 t0; t0.x = __float2half(v.x); t0.y = __float2half(v.y);
    __half2 t1; t1.x = __float2half(v.z); t1.y = __float2half(v.w);
    *(__half2*)(g_xs + i)     = t0;
    *(__half2*)(g_xs + i + 2) = t1;
}

// transpose + round to fp16: src [SR, SC] per expert -> dst [SC, SR]
template<int SR, int SC, bool W1>
__global__ void tsplit_kernel(const float* __restrict__ w)
{
    __shared__ float tile[32][33];
    int e = blockIdx.z;
    int c0 = blockIdx.x * 32;
    int r0 = blockIdx.y * 32;
    const float* src = w + (size_t)e * SR * SC;
    int tx = threadIdx.x, ty = threadIdx.y;
    #pragma unroll
    for (int j = 0; j < 32; j += 8)
        tile[ty + j][tx] = src[(size_t)(r0 + ty + j) * SC + (c0 + tx)];
    __syncthreads();
    __half* oh = (W1 ? g_w1_h : g_w2_h) + (size_t)e * SR * SC;
    #pragma unroll
    for (int j = 0; j < 32; j += 8) {
        float f = tile[tx][ty + j];
        size_t o = (size_t)(c0 + ty + j) * SR + (r0 + tx);
        oh[o] = __float2half(f);
    }
}

// ---------------- grouped fp16 mma.sync GEMM (single-pass) ----------------
// C[128,128] = A[128,K] * B[128,K]^T
template<int KTOT, bool G1>
__global__ __launch_bounds__(256, 2) void moe_mma_kernel(
    const float* __restrict__ bias, float* __restrict__ Of)
{
    constexpr int NTOT = G1 ? FDIM : DIM;
    constexpr int NCH  = KTOT / TK;

    const __half* __restrict__ Ah = G1 ? g_xs : g_h;
    const __half* __restrict__ Bh = G1 ? g_w1_h : g_w2_h;

    int e = blockIdx.z;
    int seg0 = g_offsets[e], seg1 = g_offsets[e + 1];
    int m0 = seg0 + blockIdx.y * TM;
    if (m0 >= seg1) return;
    int mcnt = min(TM, seg1 - m0);
    int n0 = blockIdx.x * TN;

    extern __shared__ char smem[];
    uint32_t sbase = smem_u32(smem);

    int tid = threadIdx.x;
    int wid = tid >> 5, lane = tid & 31;
    int warp_m = (wid >> 2) * 64;   // 0 or 64
    int warp_n = (wid & 3) * 32;    // 0,32,64,96

    const __half* Beh = Bh + (size_t)e * NTOT * KTOT;
    const float* be = bias + (size_t)e * NTOT;

    auto prefetch = [&](int it) {
        if (it < NCH) {
            int k0 = it * TK;
            uint32_t stg = sbase + (uint32_t)(it & (NSTAGE - 1)) * STAGE_BYTES;
            #pragma unroll
            for (int i = 0; i < 4; i++) {
                int c   = i * 256 + tid;          // 0..1023
                int mat = c >> 9;                 // 0:Ah 1:Bh
                int rw  = (c & 511) >> 2;         // 0..127
                int sg  = c & 3;                  // 16B segment in row
                uint32_t sa = stg + mat * MAT_BYTES + (rw * LDA + sg * 8) * 2;
                const __half* gp;
                if (mat == 0) {
                    int gr = m0 + rw;
                    if (gr > T_TOK - 1) gr = T_TOK - 1;   // clamp; never stored
                    gp = Ah + (size_t)gr * KTOT + k0 + sg * 8;
                } else {
                    gp = Beh + (size_t)(n0 + rw) * KTOT + k0 + sg * 8;
                }
                cp16(sa, gp);
            }
        }
        asm volatile("cp.async.commit_group;" ::: "memory");
    };

    float acc[4][4][4];
    #pragma unroll
    for (int i = 0; i < 4; i++)
        #pragma unroll
        for (int j = 0; j < 4; j++)
            #pragma unroll
            for (int q = 0; q < 4; q++) acc[i][j][q] = 0.f;

    prefetch(0);
    prefetch(1);
    prefetch(2);

    for (int it = 0; it < NCH; ++it) {
        asm volatile("cp.async.wait_group 2;" ::: "memory");
        __syncthreads();        // stage `it` visible; stage (it-1) reads all done
        prefetch(it + 3);       // overwrites stage (it+3)%4 == (it-1)%4 -- safe

        uint32_t stg = sbase + (uint32_t)(it & (NSTAGE - 1)) * STAGE_BYTES;
        uint32_t sAh = stg;
        uint32_t sBh = stg + MAT_BYTES;

        #pragma unroll
        for (int kst = 0; kst < 2; ++kst) {
            uint32_t afh[4][4], bfh[4][2];
            int acol = kst * 16 + ((lane >> 4) << 3);
            int arow_off = (lane & 15);
            #pragma unroll
            for (int mt = 0; mt < 4; ++mt) {
                int row = warp_m + mt * 16 + arow_off;
                uint32_t off = (uint32_t)(row * LDA + acol) * 2;
                ldm_x4(afh[mt], sAh + off);
            }
            int bcol = kst * 16 + (((lane >> 3) & 1) << 3);
            int brow_off = (lane & 7);
            #pragma unroll
            for (int nt = 0; nt < 4; ++nt) {
                int row = warp_n + nt * 8 + brow_off;
                uint32_t off = (uint32_t)(row * LDA + bcol) * 2;
                ldm_x2(bfh[nt], sBh + off);
            }
            #pragma unroll
            for (int mt = 0; mt < 4; ++mt)
                #pragma unroll
                for (int nt = 0; nt < 4; ++nt)
                    mma_f16(acc[mt][nt], afh[mt], bfh[nt]);
        }
    }

    // ---- epilogue ----
    int rbase = warp_m + (lane >> 2);
    int cbase = n0 + warp_n + (lane & 3) * 2;
    #pragma unroll
    for (int nt = 0; nt < 4; ++nt) {
        int gc = cbase + nt * 8;
        float b0 = be[gc], b1 = be[gc + 1];
        #pragma unroll
        for (int mt = 0; mt < 4; ++mt) {
            #pragma unroll
            for (int s = 0; s < 2; ++s) {
                int lr = rbase + mt * 16 + s * 8;
                if (lr < mcnt) {
                    int gr = m0 + lr;
                    float f0 = acc[mt][nt][2 * s]     + b0;
                    float f1 = acc[mt][nt][2 * s + 1] + b1;
                    if constexpr (G1) {
                        f0 = fmaxf(f0, 0.f);
                        f1 = fmaxf(f1, 0.f);
                        __half2 th;
                        th.x = __float2half(f0);
                        th.y = __float2half(f1);
                        *(__half2*)(g_h + (size_t)gr * FDIM + gc) = th;
                    } else {
                        int orow = g_perm[gr];
                        float2 v; v.x = f0; v.y = f1;
                        *(float2*)(Of + (size_t)orow * DIM + gc) = v;
                    }
                }
            }
        }
    }
}

// ---------------- launch ----------------
extern "C" void kernel_launch(void* const* d_in, const int* in_sizes, int n_in,
                              void* d_out, int out_size)
{
    const float* x  = (const float*)d_in[0];
    const float* rw = (const float*)d_in[1];
    const float* rb = (const float*)d_in[2];
    const float* w1 = (const float*)d_in[3];
    const float* b1 = (const float*)d_in[4];
    const float* w2 = (const float*)d_in[5];
    const float* b2 = (const float*)d_in[6];
    float* out = (float*)d_out;

    cudaFuncSetAttribute(moe_mma_kernel<DIM, true>,
                         cudaFuncAttributeMaxDynamicSharedMemorySize, SMEM_SZ);
    cudaFuncSetAttribute(moe_mma_kernel<FDIM, false>,
                         cudaFuncAttributeMaxDynamicSharedMemorySize, SMEM_SZ);

    init_kernel<<<1, 32>>>();
    router_kernel<<<T_TOK, 256>>>(x, rw, rb);
    prefix_kernel<<<1, 32>>>(out, out_size);
    scatter_kernel<<<(T_TOK + 255) / 256, 256>>>();

    cvt_x_kernel<<<(T_TOK * DIM / 4 + 255) / 256, 256>>>(x);
    tsplit_kernel<DIM, FDIM, true><<<dim3(FDIM / 32, DIM / 32, NE), dim3(32, 8)>>>(w1);
    tsplit_kernel<FDIM, DIM, false><<<dim3(DIM / 32, FDIM / 32, NE), dim3(32, 8)>>>(w2);

    moe_mma_kernel<DIM, true><<<dim3(FDIM / TN, T_TOK / TM, NE), 256, SMEM_SZ>>>(b1, nullptr);
    moe_mma_kernel<FDIM, false><<<dim3(DIM / TN, T_TOK / TM, NE), 256, SMEM_SZ>>>(b2, out);
}